// round 12
// baseline (speedup 1.0000x reference)
#include <cuda_runtime.h>
#include <cuda_bf16.h>
#include <stdint.h>
#include <math.h>

#define NPTS    98304
#define PER_CAM 49152
#define DH      512
#define KPAD    64
#define NBLK    5
#define FH      128
#define FW      128
#define NPIX    (FH*FW)
#define MTILES  768          // NPTS / 128

// ===================== scratch (device globals) =============================
__device__ float          g_h[(size_t)NPTS * DH];          // fp32 residual stream
__device__ float          g_featT[(size_t)2 * NPIX * DH];  // transposed features
__device__ __nv_bfloat16  g_al_hi[(size_t)NPTS * DH], g_al_lo[(size_t)NPTS * DH];
__device__ __nv_bfloat16  g_rh_hi[(size_t)NPTS * DH], g_rh_lo[(size_t)NPTS * DH];
__device__ __nv_bfloat16  g_rn_hi[(size_t)NPTS * DH], g_rn_lo[(size_t)NPTS * DH];
__device__ __nv_bfloat16  g_enc_hi[(size_t)NPTS * KPAD], g_enc_lo[(size_t)NPTS * KPAD];
__device__ __nv_bfloat16  g_wiT_hi[DH * KPAD],  g_wiT_lo[DH * KPAD];
__device__ __nv_bfloat16  g_wzT_hi[NBLK*DH*DH], g_wzT_lo[NBLK*DH*DH];
__device__ __nv_bfloat16  g_w0T_hi[NBLK*DH*DH], g_w0T_lo[NBLK*DH*DH];
__device__ __nv_bfloat16  g_w1T_hi[NBLK*DH*DH], g_w1T_lo[NBLK*DH*DH];
__device__ int            g_bidx[NPTS * 4];
__device__ float          g_bw[NPTS * 4];

__device__ __forceinline__ void split2(float v, __nv_bfloat16& hi, __nv_bfloat16& lo) {
    hi = __float2bfloat16(v);
    lo = __float2bfloat16(v - __bfloat162float(hi));
}
__device__ __forceinline__ uint32_t smem_u32(const void* p) {
    uint32_t a;
    asm("{ .reg .u64 t; cvta.to.shared.u64 t, %1; cvt.u32.u64 %0, t; }"
        : "=r"(a) : "l"(p));
    return a;
}
__device__ __forceinline__ void cp_async16(uint32_t dst, const void* src) {
    asm volatile("cp.async.cg.shared.global [%0], [%1], 16;"
                 :: "r"(dst), "l"(src) : "memory");
}
__device__ __forceinline__ void cp_commit() {
    asm volatile("cp.async.commit_group;" ::: "memory");
}
template <int N>
__device__ __forceinline__ void cp_wait() {
    asm volatile("cp.async.wait_group %0;" :: "n"(N) : "memory");
}
__device__ __forceinline__ void ldsm4(uint32_t& r0, uint32_t& r1, uint32_t& r2,
                                      uint32_t& r3, uint32_t addr) {
    asm volatile("ldmatrix.sync.aligned.m8n8.x4.shared.b16 {%0,%1,%2,%3}, [%4];"
                 : "=r"(r0), "=r"(r1), "=r"(r2), "=r"(r3) : "r"(addr));
}
__device__ __forceinline__ void mma_bf16(float* d, const uint32_t* a,
                                         const uint32_t* b) {
    asm volatile(
        "mma.sync.aligned.m16n8k16.row.col.f32.bf16.bf16.f32 "
        "{%0,%1,%2,%3}, {%4,%5,%6,%7}, {%8,%9}, {%0,%1,%2,%3};"
        : "+f"(d[0]), "+f"(d[1]), "+f"(d[2]), "+f"(d[3])
        : "r"(a[0]), "r"(a[1]), "r"(a[2]), "r"(a[3]), "r"(b[0]), "r"(b[1]));
}
// swizzled 16B-unit offset within an 8KB plane: 128 rows x 4 units of 16B
__device__ __forceinline__ uint32_t sw_off(int row, int su) {
    return (uint32_t)((row >> 1) * 128 +
                      ((((row & 1) << 2) | su) ^ ((row >> 1) & 3)) * 16);
}

// ===================== merged weight prepack (ONE launch) ===================
// lin_in: [63][512] -> g_wiT planes [512][64] (row n, col k)
// z/fc0/fc1: [5][512][512] -> [5][512][512] transposed planes
__global__ void prepack_all(const float* __restrict__ wi,
                            const float* __restrict__ wz,
                            const float* __restrict__ w0,
                            const float* __restrict__ w1) {
    int idx = blockIdx.x * 256 + threadIdx.x;
    const int NI = DH * KPAD;             // 32768
    const int NB = NBLK * DH * DH;        // 1310720
    if (idx < NI) {
        int n = idx / KPAD, k = idx % KPAD;
        float v = (k < 63) ? wi[(size_t)k * DH + n] : 0.0f;
        __nv_bfloat16 hi, lo; split2(v, hi, lo);
        g_wiT_hi[idx] = hi; g_wiT_lo[idx] = lo;
        return;
    }
    idx -= NI;
    if (idx >= 3 * NB) return;
    int which = idx / NB;
    int r     = idx % NB;
    int mat   = r / (DH * DH);
    int e     = r % (DH * DH);
    int n = e / DH, k = e % DH;
    const float* src = (which == 0) ? wz : (which == 1) ? w0 : w1;
    float v = src[(size_t)mat * DH * DH + (size_t)k * DH + n];
    __nv_bfloat16 hi, lo; split2(v, hi, lo);
    size_t o = (size_t)mat * DH * DH + (size_t)n * DH + k;
    if (which == 0)      { g_wzT_hi[o] = hi; g_wzT_lo[o] = lo; }
    else if (which == 1) { g_w0T_hi[o] = hi; g_w0T_lo[o] = lo; }
    else                 { g_w1T_hi[o] = hi; g_w1T_lo[o] = lo; }
}

// ===================== preproc: transform + projection + PE (split) =========
__global__ void preproc_kernel(const float* __restrict__ xyz,
                               const float* __restrict__ c2w,
                               const float* __restrict__ kmat) {
    int p = blockIdx.x * blockDim.x + threadIdx.x;
    if (p >= NPTS) return;
    int b = p / PER_CAM;
    const float* M  = c2w  + b * 16;
    const float* Km = kmat + b * 9;

    float d0 = xyz[p*3+0] - M[3], d1 = xyz[p*3+1] - M[7], d2 = xyz[p*3+2] - M[11];
    float cx = d0*M[0] + d1*M[4] + d2*M[8];
    float cy = d0*M[1] + d1*M[5] + d2*M[9];
    float cz = d0*M[2] + d1*M[6] + d2*M[10];

    float u = Km[0]*cx + Km[1]*cy + Km[2]*cz;
    float v = Km[3]*cx + Km[4]*cy + Km[5]*cz;
    float w = Km[6]*cx + Km[7]*cy + Km[8]*cz;
    if (fabsf(w) < 1e-6f) w = 1e-6f;
    u /= w; v /= w;

    float x = fminf(fmaxf(u, 0.f), (float)(FW-1));
    float y = fminf(fmaxf(v, 0.f), (float)(FH-1));
    float xf = floorf(x), yf = floorf(y);
    int x0 = (int)xf, y0 = (int)yf;
    int x1 = min(x0+1, FW-1), y1 = min(y0+1, FH-1);
    float wx = x - xf, wy = y - yf;

    g_bidx[p*4+0] = y0*FW + x0;  g_bidx[p*4+1] = y0*FW + x1;
    g_bidx[p*4+2] = y1*FW + x0;  g_bidx[p*4+3] = y1*FW + x1;
    g_bw[p*4+0] = (1.f-wx)*(1.f-wy);  g_bw[p*4+1] = wx*(1.f-wy);
    g_bw[p*4+2] = (1.f-wx)*wy;        g_bw[p*4+3] = wx*wy;

    float e[KPAD];
    e[0] = cx; e[1] = cy; e[2] = cz;
    float c3[3] = {cx, cy, cz};
    #pragma unroll
    for (int d = 0; d < 3; ++d) {
        float base = 6.283185307179586f * c3[d];
        float f = 1.0f;
        #pragma unroll
        for (int k = 0; k < 10; ++k) {
            float arg = base * f;
            e[3  + d*10 + k] = sinf(arg);
            e[33 + d*10 + k] = cosf(arg);
            f *= 2.0f;
        }
    }
    e[63] = 0.0f;
    __nv_bfloat16* EH = g_enc_hi + (size_t)p * KPAD;
    __nv_bfloat16* EL = g_enc_lo + (size_t)p * KPAD;
    #pragma unroll
    for (int j = 0; j < KPAD; ++j) { __nv_bfloat16 hi, lo; split2(e[j], hi, lo); EH[j]=hi; EL[j]=lo; }
}

// ===================== feature transpose [2][512][16384] -> [2][16384][512] =
__global__ void transpose_feat(const float* __restrict__ f) {
    __shared__ float tile[32][33];
    int b  = blockIdx.z;
    int c0 = blockIdx.y * 32;
    int p0 = blockIdx.x * 32;
    int tx = threadIdx.x, ty = threadIdx.y;   // 32 x 8
    const float* fb = f + (size_t)b * DH * NPIX;
    float* ob = g_featT + (size_t)b * NPIX * DH;
    #pragma unroll
    for (int i = ty; i < 32; i += 8)
        tile[i][tx] = fb[(size_t)(c0 + i) * NPIX + p0 + tx];
    __syncthreads();
    #pragma unroll
    for (int i = ty; i < 32; i += 8)
        ob[(size_t)(p0 + i) * DH + c0 + tx] = tile[tx][i];
}

// ===================== bilinear gather (coalesced via g_featT) ==============
__global__ void align_kernel() {
    int p = blockIdx.x;
    int t = threadIdx.x;   // 128 threads, 4 channels each
    int b = p / PER_CAM;
    const float* F = g_featT + (size_t)b * NPIX * DH;
    int   o0 = g_bidx[p*4+0], o1 = g_bidx[p*4+1], o2 = g_bidx[p*4+2], o3 = g_bidx[p*4+3];
    float w0 = g_bw[p*4+0],  w1 = g_bw[p*4+1],  w2 = g_bw[p*4+2],  w3 = g_bw[p*4+3];
    int c = t * 4;
    float4 f0 = *(const float4*)(F + (size_t)o0*DH + c);
    float4 f1 = *(const float4*)(F + (size_t)o1*DH + c);
    float4 f2 = *(const float4*)(F + (size_t)o2*DH + c);
    float4 f3 = *(const float4*)(F + (size_t)o3*DH + c);
    float v[4] = { w0*f0.x + w1*f1.x + w2*f2.x + w3*f3.x,
                   w0*f0.y + w1*f1.y + w2*f2.y + w3*f3.y,
                   w0*f0.z + w1*f1.z + w2*f2.z + w3*f3.z,
                   w0*f0.w + w1*f1.w + w2*f2.w + w3*f3.w };
    size_t base = (size_t)p * DH + c;
    #pragma unroll
    for (int i = 0; i < 4; ++i) {
        __nv_bfloat16 hi, lo; split2(v[i], hi, lo);
        g_al_hi[base+i] = hi; g_al_lo[base+i] = lo;
    }
}

// ===================== mma.sync GEMM ========================================
// 256 threads = 8 warps (2 M x 4 N), warp tile 64x32, K chunks of 32,
// 3-stage cp.async pipeline. Buffer: 4 planes (Ah, Al, Bh, Bl) x 8 KB = 32 KB.
// grid = (4 bn, 768 mtile): consecutive CTAs share the A tile (L2 reuse).
#define SMEM_BYTES (3 * 32768)

template <bool RES, bool OUT_H, bool SPLIT>
__global__ void __launch_bounds__(256, 2) gemm_mma(
    const __nv_bfloat16* __restrict__ Ahi, const __nv_bfloat16* __restrict__ Alo,
    const __nv_bfloat16* __restrict__ Bhi, const __nv_bfloat16* __restrict__ Blo,
    const float* __restrict__ bias, float* __restrict__ H,
    __nv_bfloat16* __restrict__ Ohi, __nv_bfloat16* __restrict__ Olo, int K) {
    extern __shared__ __align__(1024) char smem[];
    const uint32_t sb = smem_u32(smem);
    const int tid  = threadIdx.x;
    const int wid  = tid >> 5, lane = tid & 31;
    const int bn   = blockIdx.x * 128;
    const int bm   = blockIdx.y * 128;
    const int wm   = wid & 1;          // M half  (64 rows)
    const int wn   = wid >> 1;         // N quarter (32 cols)

    float acc[4][4][4];
    #pragma unroll
    for (int i = 0; i < 4; ++i)
        #pragma unroll
        for (int j = 0; j < 4; ++j)
            #pragma unroll
            for (int q = 0; q < 4; ++q) acc[i][j][q] = 0.0f;

    const int nchunk = K >> 5;

    auto load_chunk = [&](int c, int buf) {
        const int kc = c * 32;
        const uint32_t base = sb + buf * 32768;
        #pragma unroll
        for (int i = 0; i < 8; ++i) {
            int u     = tid + i * 256;        // 0..2047
            int plane = u >> 9;
            int pu    = u & 511;
            int row   = pu >> 2;
            int su    = pu & 3;
            uint32_t dst = base + plane * 8192 + sw_off(row, su);
            const __nv_bfloat16* src;
            if      (plane == 0) src = Ahi + (size_t)(bm + row) * K + kc + su * 8;
            else if (plane == 1) src = Alo + (size_t)(bm + row) * K + kc + su * 8;
            else if (plane == 2) src = Bhi + (size_t)(bn + row) * K + kc + su * 8;
            else                 src = Blo + (size_t)(bn + row) * K + kc + su * 8;
            cp_async16(dst, src);
        }
        cp_commit();
    };

    load_chunk(0, 0);
    if (nchunk > 1) load_chunk(1, 1);

    int buf = 0;
    for (int c = 0; c < nchunk; ++c) {
        if (c + 2 < nchunk) {
            int nb = buf + 2; if (nb >= 3) nb -= 3;
            load_chunk(c + 2, nb);
        }
        int rem = nchunk - 1 - c;
        if (rem >= 2) cp_wait<2>(); else if (rem == 1) cp_wait<1>(); else cp_wait<0>();
        __syncthreads();

        const uint32_t bufb = sb + buf * 32768;
        const uint32_t Ahb = bufb, Alb = bufb + 8192;
        const uint32_t Bhb = bufb + 16384, Blb = bufb + 24576;
        #pragma unroll
        for (int k16 = 0; k16 < 2; ++k16) {
            const int asu = k16 * 2 + (lane >> 4);
            const int arow = wm * 64 + (lane & 15);
            const int bsu = k16 * 2 + ((lane >> 3) & 1);
            const int brow = wn * 32 + ((lane >> 4) << 3) + (lane & 7);

            uint32_t ah[4][4];
            #pragma unroll
            for (int mf = 0; mf < 4; ++mf)
                ldsm4(ah[mf][0], ah[mf][1], ah[mf][2], ah[mf][3],
                      Ahb + sw_off(arow + mf * 16, asu));
            uint32_t bh[4][2];
            #pragma unroll
            for (int nf2 = 0; nf2 < 2; ++nf2) {
                uint32_t r0, r1, r2, r3;
                ldsm4(r0, r1, r2, r3, Bhb + sw_off(brow + nf2 * 16, bsu));
                bh[nf2*2][0] = r0; bh[nf2*2][1] = r1;
                bh[nf2*2+1][0] = r2; bh[nf2*2+1][1] = r3;
            }
            #pragma unroll
            for (int mf = 0; mf < 4; ++mf)
                #pragma unroll
                for (int nf = 0; nf < 4; ++nf)
                    mma_bf16(acc[mf][nf], ah[mf], bh[nf]);

            uint32_t bl[4][2];
            #pragma unroll
            for (int nf2 = 0; nf2 < 2; ++nf2) {
                uint32_t r0, r1, r2, r3;
                ldsm4(r0, r1, r2, r3, Blb + sw_off(brow + nf2 * 16, bsu));
                bl[nf2*2][0] = r0; bl[nf2*2][1] = r1;
                bl[nf2*2+1][0] = r2; bl[nf2*2+1][1] = r3;
            }
            #pragma unroll
            for (int mf = 0; mf < 4; ++mf)
                #pragma unroll
                for (int nf = 0; nf < 4; ++nf)
                    mma_bf16(acc[mf][nf], ah[mf], bl[nf]);

            uint32_t al[4][4];
            #pragma unroll
            for (int mf = 0; mf < 4; ++mf)
                ldsm4(al[mf][0], al[mf][1], al[mf][2], al[mf][3],
                      Alb + sw_off(arow + mf * 16, asu));
            #pragma unroll
            for (int mf = 0; mf < 4; ++mf)
                #pragma unroll
                for (int nf = 0; nf < 4; ++nf)
                    mma_bf16(acc[mf][nf], al[mf], bh[nf]);
        }
        __syncthreads();
        if (++buf >= 3) buf = 0;
    }

    // ---- epilogue ----
    float2 bias2[4];
    #pragma unroll
    for (int nf = 0; nf < 4; ++nf)
        bias2[nf] = *(const float2*)(bias + bn + wn * 32 + nf * 8 + (lane & 3) * 2);

    #pragma unroll
    for (int mf = 0; mf < 4; ++mf) {
        #pragma unroll
        for (int half = 0; half < 2; ++half) {
            int row = bm + wm * 64 + mf * 16 + (lane >> 2) + half * 8;
            #pragma unroll
            for (int nf = 0; nf < 4; ++nf) {
                int col = bn + wn * 32 + nf * 8 + (lane & 3) * 2;
                size_t off = (size_t)row * DH + col;
                float v0 = acc[mf][nf][half * 2 + 0] + bias2[nf].x;
                float v1 = acc[mf][nf][half * 2 + 1] + bias2[nf].y;
                if (RES) {
                    float2 hv = *(const float2*)(H + off);
                    v0 += hv.x; v1 += hv.y;
                }
                if (OUT_H) *(float2*)(H + off) = make_float2(v0, v1);
                if (SPLIT) {
                    float r0 = fmaxf(v0, 0.0f), r1 = fmaxf(v1, 0.0f);
                    __nv_bfloat16 h0, l0, h1, l1;
                    split2(r0, h0, l0); split2(r1, h1, l1);
                    __nv_bfloat162 hh; hh.x = h0; hh.y = h1;
                    __nv_bfloat162 ll; ll.x = l0; ll.y = l1;
                    *(__nv_bfloat162*)(Ohi + off) = hh;
                    *(__nv_bfloat162*)(Olo + off) = ll;
                }
            }
        }
    }
}

// ===================== head: out = exp(relu(h) @ w_out + b_out) =============
__global__ void final_kernel(const float* __restrict__ wout,
                             const float* __restrict__ bout,
                             float* __restrict__ out) {
    int p = blockIdx.x;
    int t = threadIdx.x;  // 128
    const float* Hp = g_h + (size_t)p * DH;
    float s = 0.0f;
    #pragma unroll
    for (int i = 0; i < 4; ++i) {
        int c = t + i * 128;
        s += fmaxf(Hp[c], 0.0f) * wout[c];
    }
    #pragma unroll
    for (int o = 16; o > 0; o >>= 1) s += __shfl_down_sync(0xffffffffu, s, o);
    __shared__ float red[4];
    if ((t & 31) == 0) red[t >> 5] = s;
    __syncthreads();
    if (t == 0) out[p] = expf(red[0] + red[1] + red[2] + red[3] + bout[0]);
}

// ===========================================================================
extern "C" void kernel_launch(void* const* d_in, const int* in_sizes, int n_in,
                              void* d_out, int out_size) {
    const float* world_xyz = (const float*)d_in[0];
    const float* c2w       = (const float*)d_in[1];
    const float* kmat      = (const float*)d_in[2];
    const float* features  = (const float*)d_in[3];
    const float* lin_in_w  = (const float*)d_in[4];
    const float* lin_in_b  = (const float*)d_in[5];
    const float* lin_z_w   = (const float*)d_in[6];
    const float* lin_z_b   = (const float*)d_in[7];
    const float* fc0_w     = (const float*)d_in[8];
    const float* fc0_b     = (const float*)d_in[9];
    const float* fc1_w     = (const float*)d_in[10];
    const float* fc1_b     = (const float*)d_in[11];
    const float* lin_out_w = (const float*)d_in[12];
    const float* lin_out_b = (const float*)d_in[13];
    float* out = (float*)d_out;

    float *p_h;
    __nv_bfloat16 *p_alh, *p_all, *p_rhh, *p_rhl, *p_rnh, *p_rnl;
    __nv_bfloat16 *p_ench, *p_encl, *p_wih, *p_wil;
    __nv_bfloat16 *p_wzh, *p_wzl, *p_w0h, *p_w0l, *p_w1h, *p_w1l;
    cudaGetSymbolAddress((void**)&p_h,    g_h);
    cudaGetSymbolAddress((void**)&p_alh,  g_al_hi);  cudaGetSymbolAddress((void**)&p_all,  g_al_lo);
    cudaGetSymbolAddress((void**)&p_rhh,  g_rh_hi);  cudaGetSymbolAddress((void**)&p_rhl,  g_rh_lo);
    cudaGetSymbolAddress((void**)&p_rnh,  g_rn_hi);  cudaGetSymbolAddress((void**)&p_rnl,  g_rn_lo);
    cudaGetSymbolAddress((void**)&p_ench, g_enc_hi); cudaGetSymbolAddress((void**)&p_encl, g_enc_lo);
    cudaGetSymbolAddress((void**)&p_wih,  g_wiT_hi); cudaGetSymbolAddress((void**)&p_wil,  g_wiT_lo);
    cudaGetSymbolAddress((void**)&p_wzh,  g_wzT_hi); cudaGetSymbolAddress((void**)&p_wzl,  g_wzT_lo);
    cudaGetSymbolAddress((void**)&p_w0h,  g_w0T_hi); cudaGetSymbolAddress((void**)&p_w0l,  g_w0T_lo);
    cudaGetSymbolAddress((void**)&p_w1h,  g_w1T_hi); cudaGetSymbolAddress((void**)&p_w1l,  g_w1T_lo);

    cudaFuncSetAttribute(gemm_mma<false, true,  false>, cudaFuncAttributeMaxDynamicSharedMemorySize, SMEM_BYTES);
    cudaFuncSetAttribute(gemm_mma<true,  true,  true >, cudaFuncAttributeMaxDynamicSharedMemorySize, SMEM_BYTES);
    cudaFuncSetAttribute(gemm_mma<false, false, true >, cudaFuncAttributeMaxDynamicSharedMemorySize, SMEM_BYTES);
    cudaFuncSetAttribute(gemm_mma<true,  true,  false>, cudaFuncAttributeMaxDynamicSharedMemorySize, SMEM_BYTES);

    // launch 0: merged weight prepack
    {
        int total = DH * KPAD + 3 * NBLK * DH * DH;
        prepack_all<<<(total + 255) / 256, 256>>>(lin_in_w, lin_z_w, fc0_w, fc1_w);
    }
    // launch 1-3
    preproc_kernel<<<(NPTS + 255) / 256, 256>>>(world_xyz, c2w, kmat);
    transpose_feat<<<dim3(NPIX / 32, DH / 32, 2), dim3(32, 8)>>>(features);
    align_kernel<<<NPTS, 128>>>();

    dim3 gg(4, MTILES);   // x = bn (4), y = mtile (768): A-tile L2 reuse

    // launch 4: h = enc @ W_in + b          (K = 64)
    gemm_mma<false, true, false><<<gg, 256, SMEM_BYTES>>>(
        p_ench, p_encl, p_wih, p_wil, lin_in_b, p_h, nullptr, nullptr, KPAD);

    // launch 5 = first mainloop GEMM (ncu -s 5 -c 1 profiles this)
    for (int i = 0; i < NBLK; ++i) {
        size_t o = (size_t)i * DH * DH;
        // h += aligned @ zw + zb ;  emit relu(h) split
        gemm_mma<true, true, true><<<gg, 256, SMEM_BYTES>>>(
            p_alh, p_all, p_wzh + o, p_wzl + o, lin_z_b + (size_t)i * DH,
            p_h, p_rhh, p_rhl, DH);
        // net = relu(h) @ fc0 + b0 ;  emit relu(net) split only
        gemm_mma<false, false, true><<<gg, 256, SMEM_BYTES>>>(
            p_rhh, p_rhl, p_w0h + o, p_w0l + o, fc0_b + (size_t)i * DH,
            p_h, p_rnh, p_rnl, DH);
        // h += relu(net) @ fc1 + b1
        gemm_mma<true, true, false><<<gg, 256, SMEM_BYTES>>>(
            p_rnh, p_rnl, p_w1h + o, p_w1l + o, fc1_b + (size_t)i * DH,
            p_h, nullptr, nullptr, DH);
    }

    final_kernel<<<NPTS, 128>>>(lin_out_w, lin_out_b, out);
}

// round 14
// speedup vs baseline: 1.4972x; 1.4972x over previous
#include <cuda_runtime.h>
#include <cuda_bf16.h>
#include <stdint.h>
#include <math.h>

#define NPTS    98304
#define PER_CAM 49152
#define DH      512
#define KPAD    64
#define NBLK    5
#define FH      128
#define FW      128
#define NPIX    (FH*FW)
#define MTILES  768          // NPTS / 128

// ===================== scratch (device globals) =============================
__device__ float          g_h[(size_t)NPTS * DH];          // fp32 residual stream
__device__ float          g_featT[(size_t)2 * NPIX * DH];  // transposed features
__device__ __nv_bfloat16  g_al_hi[(size_t)NPTS * DH], g_al_lo[(size_t)NPTS * DH];
__device__ __nv_bfloat16  g_rh_hi[(size_t)NPTS * DH], g_rh_lo[(size_t)NPTS * DH];
__device__ __nv_bfloat16  g_rn_hi[(size_t)NPTS * DH], g_rn_lo[(size_t)NPTS * DH];
__device__ __nv_bfloat16  g_enc_hi[(size_t)NPTS * KPAD], g_enc_lo[(size_t)NPTS * KPAD];
__device__ __nv_bfloat16  g_wiT_hi[DH * KPAD],  g_wiT_lo[DH * KPAD];
__device__ __nv_bfloat16  g_wzT_hi[NBLK*DH*DH], g_wzT_lo[NBLK*DH*DH];
__device__ __nv_bfloat16  g_w0T_hi[NBLK*DH*DH], g_w0T_lo[NBLK*DH*DH];
__device__ __nv_bfloat16  g_w1T_hi[NBLK*DH*DH], g_w1T_lo[NBLK*DH*DH];

__device__ __forceinline__ void split2(float v, __nv_bfloat16& hi, __nv_bfloat16& lo) {
    hi = __float2bfloat16(v);
    lo = __float2bfloat16(v - __bfloat162float(hi));
}
__device__ __forceinline__ uint32_t smem_u32(const void* p) {
    uint32_t a;
    asm("{ .reg .u64 t; cvta.to.shared.u64 t, %1; cvt.u32.u64 %0, t; }"
        : "=r"(a) : "l"(p));
    return a;
}
__device__ __forceinline__ void cp_async16(uint32_t dst, const void* src) {
    asm volatile("cp.async.cg.shared.global [%0], [%1], 16;"
                 :: "r"(dst), "l"(src) : "memory");
}
__device__ __forceinline__ void cp_commit() {
    asm volatile("cp.async.commit_group;" ::: "memory");
}
template <int N>
__device__ __forceinline__ void cp_wait() {
    asm volatile("cp.async.wait_group %0;" :: "n"(N) : "memory");
}
__device__ __forceinline__ void ldsm4(uint32_t& r0, uint32_t& r1, uint32_t& r2,
                                      uint32_t& r3, uint32_t addr) {
    asm volatile("ldmatrix.sync.aligned.m8n8.x4.shared.b16 {%0,%1,%2,%3}, [%4];"
                 : "=r"(r0), "=r"(r1), "=r"(r2), "=r"(r3) : "r"(addr));
}
__device__ __forceinline__ void mma_bf16(float* d, const uint32_t* a,
                                         const uint32_t* b) {
    asm volatile(
        "mma.sync.aligned.m16n8k16.row.col.f32.bf16.bf16.f32 "
        "{%0,%1,%2,%3}, {%4,%5,%6,%7}, {%8,%9}, {%0,%1,%2,%3};"
        : "+f"(d[0]), "+f"(d[1]), "+f"(d[2]), "+f"(d[3])
        : "r"(a[0]), "r"(a[1]), "r"(a[2]), "r"(a[3]), "r"(b[0]), "r"(b[1]));
}
// swizzled 16B-unit offset within an 8KB plane: 128 rows x 4 units of 16B
__device__ __forceinline__ uint32_t sw_off(int row, int su) {
    return (uint32_t)((row >> 1) * 128 +
                      ((((row & 1) << 2) | su) ^ ((row >> 1) & 3)) * 16);
}

// ===================== merged weight prepack (ONE launch) ===================
__global__ void prepack_all(const float* __restrict__ wi,
                            const float* __restrict__ wz,
                            const float* __restrict__ w0,
                            const float* __restrict__ w1) {
    int idx = blockIdx.x * 256 + threadIdx.x;
    const int NI = DH * KPAD;             // 32768
    const int NB = NBLK * DH * DH;        // 1310720
    if (idx < NI) {
        int n = idx / KPAD, k = idx % KPAD;
        float v = (k < 63) ? wi[(size_t)k * DH + n] : 0.0f;
        __nv_bfloat16 hi, lo; split2(v, hi, lo);
        g_wiT_hi[idx] = hi; g_wiT_lo[idx] = lo;
        return;
    }
    idx -= NI;
    if (idx >= 3 * NB) return;
    int which = idx / NB;
    int r     = idx % NB;
    int mat   = r / (DH * DH);
    int e     = r % (DH * DH);
    int n = e / DH, k = e % DH;
    const float* src = (which == 0) ? wz : (which == 1) ? w0 : w1;
    float v = src[(size_t)mat * DH * DH + (size_t)k * DH + n];
    __nv_bfloat16 hi, lo; split2(v, hi, lo);
    size_t o = (size_t)mat * DH * DH + (size_t)n * DH + k;
    if (which == 0)      { g_wzT_hi[o] = hi; g_wzT_lo[o] = lo; }
    else if (which == 1) { g_w0T_hi[o] = hi; g_w0T_lo[o] = lo; }
    else                 { g_w1T_hi[o] = hi; g_w1T_lo[o] = lo; }
}

// ===================== feature transpose [2][512][16384] -> [2][16384][512] =
__global__ void transpose_feat(const float* __restrict__ f) {
    __shared__ float tile[32][33];
    int b  = blockIdx.z;
    int c0 = blockIdx.y * 32;
    int p0 = blockIdx.x * 32;
    int tx = threadIdx.x, ty = threadIdx.y;   // 32 x 8
    const float* fb = f + (size_t)b * DH * NPIX;
    float* ob = g_featT + (size_t)b * NPIX * DH;
    #pragma unroll
    for (int i = ty; i < 32; i += 8)
        tile[i][tx] = fb[(size_t)(c0 + i) * NPIX + p0 + tx];
    __syncthreads();
    #pragma unroll
    for (int i = ty; i < 32; i += 8)
        ob[(size_t)(p0 + i) * DH + c0 + tx] = tile[tx][i];
}

// ===================== fused preproc + bilinear gather ======================
// block = point (128 threads). Thread 0: camera transform + projection;
// threads 0-29: sin/cos PE; threads 0-63: enc split store; all: 512-ch gather.
__global__ void pre_align_kernel(const float* __restrict__ xyz,
                                 const float* __restrict__ c2w,
                                 const float* __restrict__ kmat) {
    int p = blockIdx.x;
    int t = threadIdx.x;
    int b = p / PER_CAM;
    __shared__ float s_c3[3];
    __shared__ float s_w[4];
    __shared__ int   s_o[4];
    __shared__ float s_e[KPAD];

    if (t == 0) {
        const float* M  = c2w  + b * 16;
        const float* Km = kmat + b * 9;
        float d0 = xyz[p*3+0] - M[3], d1 = xyz[p*3+1] - M[7], d2 = xyz[p*3+2] - M[11];
        float cx = d0*M[0] + d1*M[4] + d2*M[8];
        float cy = d0*M[1] + d1*M[5] + d2*M[9];
        float cz = d0*M[2] + d1*M[6] + d2*M[10];

        float u = Km[0]*cx + Km[1]*cy + Km[2]*cz;
        float v = Km[3]*cx + Km[4]*cy + Km[5]*cz;
        float w = Km[6]*cx + Km[7]*cy + Km[8]*cz;
        if (fabsf(w) < 1e-6f) w = 1e-6f;
        u /= w; v /= w;

        float x = fminf(fmaxf(u, 0.f), (float)(FW-1));
        float y = fminf(fmaxf(v, 0.f), (float)(FH-1));
        float xf = floorf(x), yf = floorf(y);
        int x0 = (int)xf, y0 = (int)yf;
        int x1 = min(x0+1, FW-1), y1 = min(y0+1, FH-1);
        float wx = x - xf, wy = y - yf;

        s_o[0] = y0*FW + x0;  s_o[1] = y0*FW + x1;
        s_o[2] = y1*FW + x0;  s_o[3] = y1*FW + x1;
        s_w[0] = (1.f-wx)*(1.f-wy);  s_w[1] = wx*(1.f-wy);
        s_w[2] = (1.f-wx)*wy;        s_w[3] = wx*wy;
        s_c3[0] = cx; s_c3[1] = cy; s_c3[2] = cz;
        s_e[0] = cx; s_e[1] = cy; s_e[2] = cz;
        s_e[63] = 0.0f;
    }
    __syncthreads();
    if (t < 30) {
        int d = t / 10, k = t % 10;
        float base = 6.283185307179586f * s_c3[d];
        float arg  = base * (float)(1 << k);
        s_e[3  + d*10 + k] = sinf(arg);
        s_e[33 + d*10 + k] = cosf(arg);
    }
    __syncthreads();
    if (t < KPAD) {
        __nv_bfloat16 hi, lo; split2(s_e[t], hi, lo);
        g_enc_hi[(size_t)p * KPAD + t] = hi;
        g_enc_lo[(size_t)p * KPAD + t] = lo;
    }

    const float* F = g_featT + (size_t)b * NPIX * DH;
    float w0 = s_w[0], w1 = s_w[1], w2 = s_w[2], w3 = s_w[3];
    int   o0 = s_o[0], o1 = s_o[1], o2 = s_o[2], o3 = s_o[3];
    int c = t * 4;
    float4 f0 = *(const float4*)(F + (size_t)o0*DH + c);
    float4 f1 = *(const float4*)(F + (size_t)o1*DH + c);
    float4 f2 = *(const float4*)(F + (size_t)o2*DH + c);
    float4 f3 = *(const float4*)(F + (size_t)o3*DH + c);
    float v[4] = { w0*f0.x + w1*f1.x + w2*f2.x + w3*f3.x,
                   w0*f0.y + w1*f1.y + w2*f2.y + w3*f3.y,
                   w0*f0.z + w1*f1.z + w2*f2.z + w3*f3.z,
                   w0*f0.w + w1*f1.w + w2*f2.w + w3*f3.w };
    size_t base = (size_t)p * DH + c;
    #pragma unroll
    for (int i = 0; i < 4; ++i) {
        __nv_bfloat16 hi, lo; split2(v[i], hi, lo);
        g_al_hi[base+i] = hi; g_al_lo[base+i] = lo;
    }
}

// ===================== mma.sync GEMM (R11-proven mainloop) ==================
// 256 threads = 8 warps (2 M x 4 N), warp tile 64x32, K chunks of 32,
// cp.async double buffer. Buffer: 4 planes (Ah, Al, Bh, Bl) x 8 KB = 32 KB.
// grid = (4 bn, 768 mtile): consecutive CTAs share the A tile (L2 reuse).
#define SMEM_BYTES 65536

template <bool RES, bool OUT_H, bool SPLIT>
__global__ void __launch_bounds__(256, 2) gemm_mma(
    const __nv_bfloat16* __restrict__ Ahi, const __nv_bfloat16* __restrict__ Alo,
    const __nv_bfloat16* __restrict__ Bhi, const __nv_bfloat16* __restrict__ Blo,
    const float* __restrict__ bias, float* __restrict__ H,
    __nv_bfloat16* __restrict__ Ohi, __nv_bfloat16* __restrict__ Olo, int K) {
    extern __shared__ __align__(1024) char smem[];
    const uint32_t sb = smem_u32(smem);
    const int tid  = threadIdx.x;
    const int wid  = tid >> 5, lane = tid & 31;
    const int bn   = blockIdx.x * 128;
    const int bm   = blockIdx.y * 128;
    const int wm   = wid & 1;          // M half  (64 rows)
    const int wn   = wid >> 1;         // N quarter (32 cols)

    float acc[4][4][4];
    #pragma unroll
    for (int i = 0; i < 4; ++i)
        #pragma unroll
        for (int j = 0; j < 4; ++j)
            #pragma unroll
            for (int q = 0; q < 4; ++q) acc[i][j][q] = 0.0f;

    const int nchunk = K >> 5;

    auto load_chunk = [&](int c, int buf) {
        const int kc = c * 32;
        const uint32_t base = sb + buf * 32768;
        #pragma unroll
        for (int i = 0; i < 8; ++i) {
            int u     = tid + i * 256;        // 0..2047
            int plane = u >> 9;
            int pu    = u & 511;
            int row   = pu >> 2;
            int su    = pu & 3;
            uint32_t dst = base + plane * 8192 + sw_off(row, su);
            const __nv_bfloat16* src;
            if      (plane == 0) src = Ahi + (size_t)(bm + row) * K + kc + su * 8;
            else if (plane == 1) src = Alo + (size_t)(bm + row) * K + kc + su * 8;
            else if (plane == 2) src = Bhi + (size_t)(bn + row) * K + kc + su * 8;
            else                 src = Blo + (size_t)(bn + row) * K + kc + su * 8;
            cp_async16(dst, src);
        }
        cp_commit();
    };

    load_chunk(0, 0);

    for (int c = 0; c < nchunk; ++c) {
        if (c + 1 < nchunk) load_chunk(c + 1, (c + 1) & 1);
        if (c + 1 < nchunk) cp_wait<1>(); else cp_wait<0>();
        __syncthreads();

        const uint32_t buf = sb + (c & 1) * 32768;
        #pragma unroll
        for (int pass = 0; pass < 3; ++pass) {
            const uint32_t Ab = buf + (pass == 2 ? 8192 : 0);
            const uint32_t Bb = buf + 16384 + (pass == 1 ? 8192 : 0);
            #pragma unroll
            for (int k16 = 0; k16 < 2; ++k16) {
                uint32_t a[4][4];
                #pragma unroll
                for (int mf = 0; mf < 4; ++mf) {
                    int row = wm * 64 + mf * 16 + (lane & 15);
                    int su  = k16 * 2 + (lane >> 4);
                    ldsm4(a[mf][0], a[mf][1], a[mf][2], a[mf][3],
                          Ab + sw_off(row, su));
                }
                uint32_t b[4][2];
                #pragma unroll
                for (int nf2 = 0; nf2 < 2; ++nf2) {
                    int row = wn * 32 + nf2 * 16 + ((lane >> 4) << 3) + (lane & 7);
                    int su  = k16 * 2 + ((lane >> 3) & 1);
                    uint32_t r0, r1, r2, r3;
                    ldsm4(r0, r1, r2, r3, Bb + sw_off(row, su));
                    b[nf2*2][0]   = r0; b[nf2*2][1]   = r1;
                    b[nf2*2+1][0] = r2; b[nf2*2+1][1] = r3;
                }
                #pragma unroll
                for (int mf = 0; mf < 4; ++mf)
                    #pragma unroll
                    for (int nf = 0; nf < 4; ++nf)
                        mma_bf16(acc[mf][nf], a[mf], b[nf]);
            }
        }
        __syncthreads();
    }

    // ---- epilogue ----
    float2 bias2[4];
    #pragma unroll
    for (int nf = 0; nf < 4; ++nf)
        bias2[nf] = *(const float2*)(bias + bn + wn * 32 + nf * 8 + (lane & 3) * 2);

    #pragma unroll
    for (int mf = 0; mf < 4; ++mf) {
        #pragma unroll
        for (int half = 0; half < 2; ++half) {
            int row = bm + wm * 64 + mf * 16 + (lane >> 2) + half * 8;
            #pragma unroll
            for (int nf = 0; nf < 4; ++nf) {
                int col = bn + wn * 32 + nf * 8 + (lane & 3) * 2;
                size_t off = (size_t)row * DH + col;
                float v0 = acc[mf][nf][half * 2 + 0] + bias2[nf].x;
                float v1 = acc[mf][nf][half * 2 + 1] + bias2[nf].y;
                if (RES) {
                    float2 hv = *(const float2*)(H + off);
                    v0 += hv.x; v1 += hv.y;
                }
                if (OUT_H) *(float2*)(H + off) = make_float2(v0, v1);
                if (SPLIT) {
                    float r0 = fmaxf(v0, 0.0f), r1 = fmaxf(v1, 0.0f);
                    __nv_bfloat16 h0, l0, h1, l1;
                    split2(r0, h0, l0); split2(r1, h1, l1);
                    __nv_bfloat162 hh; hh.x = h0; hh.y = h1;
                    __nv_bfloat162 ll; ll.x = l0; ll.y = l1;
                    *(__nv_bfloat162*)(Ohi + off) = hh;
                    *(__nv_bfloat162*)(Olo + off) = ll;
                }
            }
        }
    }
}

// ===================== head: out = exp(relu(h) @ w_out + b_out) =============
__global__ void final_kernel(const float* __restrict__ wout,
                             const float* __restrict__ bout,
                             float* __restrict__ out) {
    int p = blockIdx.x;
    int t = threadIdx.x;  // 128
    const float* Hp = g_h + (size_t)p * DH;
    float s = 0.0f;
    #pragma unroll
    for (int i = 0; i < 4; ++i) {
        int c = t + i * 128;
        s += fmaxf(Hp[c], 0.0f) * wout[c];
    }
    #pragma unroll
    for (int o = 16; o > 0; o >>= 1) s += __shfl_down_sync(0xffffffffu, s, o);
    __shared__ float red[4];
    if ((t & 31) == 0) red[t >> 5] = s;
    __syncthreads();
    if (t == 0) out[p] = expf(red[0] + red[1] + red[2] + red[3] + bout[0]);
}

// ===========================================================================
extern "C" void kernel_launch(void* const* d_in, const int* in_sizes, int n_in,
                              void* d_out, int out_size) {
    const float* world_xyz = (const float*)d_in[0];
    const float* c2w       = (const float*)d_in[1];
    const float* kmat      = (const float*)d_in[2];
    const float* features  = (const float*)d_in[3];
    const float* lin_in_w  = (const float*)d_in[4];
    const float* lin_in_b  = (const float*)d_in[5];
    const float* lin_z_w   = (const float*)d_in[6];
    const float* lin_z_b   = (const float*)d_in[7];
    const float* fc0_w     = (const float*)d_in[8];
    const float* fc0_b     = (const float*)d_in[9];
    const float* fc1_w     = (const float*)d_in[10];
    const float* fc1_b     = (const float*)d_in[11];
    const float* lin_out_w = (const float*)d_in[12];
    const float* lin_out_b = (const float*)d_in[13];
    float* out = (float*)d_out;

    float *p_h;
    __nv_bfloat16 *p_alh, *p_all, *p_rhh, *p_rhl, *p_rnh, *p_rnl;
    __nv_bfloat16 *p_ench, *p_encl, *p_wih, *p_wil;
    __nv_bfloat16 *p_wzh, *p_wzl, *p_w0h, *p_w0l, *p_w1h, *p_w1l;
    cudaGetSymbolAddress((void**)&p_h,    g_h);
    cudaGetSymbolAddress((void**)&p_alh,  g_al_hi);  cudaGetSymbolAddress((void**)&p_all,  g_al_lo);
    cudaGetSymbolAddress((void**)&p_rhh,  g_rh_hi);  cudaGetSymbolAddress((void**)&p_rhl,  g_rh_lo);
    cudaGetSymbolAddress((void**)&p_rnh,  g_rn_hi);  cudaGetSymbolAddress((void**)&p_rnl,  g_rn_lo);
    cudaGetSymbolAddress((void**)&p_ench, g_enc_hi); cudaGetSymbolAddress((void**)&p_encl, g_enc_lo);
    cudaGetSymbolAddress((void**)&p_wih,  g_wiT_hi); cudaGetSymbolAddress((void**)&p_wil,  g_wiT_lo);
    cudaGetSymbolAddress((void**)&p_wzh,  g_wzT_hi); cudaGetSymbolAddress((void**)&p_wzl,  g_wzT_lo);
    cudaGetSymbolAddress((void**)&p_w0h,  g_w0T_hi); cudaGetSymbolAddress((void**)&p_w0l,  g_w0T_lo);
    cudaGetSymbolAddress((void**)&p_w1h,  g_w1T_hi); cudaGetSymbolAddress((void**)&p_w1l,  g_w1T_lo);

    cudaFuncSetAttribute(gemm_mma<false, true,  false>, cudaFuncAttributeMaxDynamicSharedMemorySize, SMEM_BYTES);
    cudaFuncSetAttribute(gemm_mma<true,  true,  true >, cudaFuncAttributeMaxDynamicSharedMemorySize, SMEM_BYTES);
    cudaFuncSetAttribute(gemm_mma<false, false, true >, cudaFuncAttributeMaxDynamicSharedMemorySize, SMEM_BYTES);
    cudaFuncSetAttribute(gemm_mma<true,  true,  false>, cudaFuncAttributeMaxDynamicSharedMemorySize, SMEM_BYTES);

    // launch 0: merged weight prepack
    {
        int total = DH * KPAD + 3 * NBLK * DH * DH;
        prepack_all<<<(total + 255) / 256, 256>>>(lin_in_w, lin_z_w, fc0_w, fc1_w);
    }
    // launch 1: feature transpose
    transpose_feat<<<dim3(NPIX / 32, DH / 32, 2), dim3(32, 8)>>>(features);
    // launch 2: fused preproc + gather
    pre_align_kernel<<<NPTS, 128>>>(world_xyz, c2w, kmat);

    dim3 gg(4, MTILES);   // x = bn (4), y = mtile (768): A-tile L2 reuse

    // launch 3: h = enc @ W_in + b  (K = 64)  <- ncu profile target
    gemm_mma<false, true, false><<<gg, 256, SMEM_BYTES>>>(
        p_ench, p_encl, p_wih, p_wil, lin_in_b, p_h, nullptr, nullptr, KPAD);

    for (int i = 0; i < NBLK; ++i) {
        size_t o = (size_t)i * DH * DH;
        // h += aligned @ zw + zb ;  emit relu(h) split
        gemm_mma<true, true, true><<<gg, 256, SMEM_BYTES>>>(
            p_alh, p_all, p_wzh + o, p_wzl + o, lin_z_b + (size_t)i * DH,
            p_h, p_rhh, p_rhl, DH);
        // net = relu(h) @ fc0 + b0 ;  emit relu(net) split only
        gemm_mma<false, false, true><<<gg, 256, SMEM_BYTES>>>(
            p_rhh, p_rhl, p_w0h + o, p_w0l + o, fc0_b + (size_t)i * DH,
            p_h, p_rnh, p_rnl, DH);
        // h += relu(net) @ fc1 + b1
        gemm_mma<true, true, false><<<gg, 256, SMEM_BYTES>>>(
            p_rnh, p_rnl, p_w1h + o, p_w1l + o, fc1_b + (size_t)i * DH,
            p_h, nullptr, nullptr, DH);
    }

    final_kernel<<<NPTS, 128>>>(lin_out_w, lin_out_b, out);
}